// round 9
// baseline (speedup 1.0000x reference)
#include <cuda_runtime.h>
#include <cuda_bf16.h>
#include <cstdint>
#include <math.h>

// ---------------- problem constants ----------------
#define TSTEPS 512
#define BATCH  64
#define DIN    1024
#define DHID   1024

// ---------------- persistent-loop config ----------------
#define NCTA 128                 // persistent CTAs; CTA owns 8 hidden dims = 32 gemm cols
#define NTHR 256                 // 8 warps: mgroup = wid&1, kslice = wid>>1
#define NCHL 16                  // recurrent K chunks (1024/64)

// loop SMEM layout (bytes)
#define ZSTG    16384            // per stage: zhi 8K | zlo 8K
#define NSTG    3
#define WOFF    (NSTG * ZSTG)                // 49152 : W_h resident 128KB
#define PX_OFF  (WOFF + 131072)              // 180224: px 64x33 floats = 8448
#define PP_STRIDE 34
#define PP_SLICE  (BATCH * PP_STRIDE)        // 2176 floats per k-slice
#define PP_OFF  (PX_OFF + 8448)              // 188672: pre_part [4][2176] floats = 34816
#define C_OFF   (PP_OFF + 34816)             // 223488: c state 512 floats
#define BIAS_OFF (C_OFF + 2048)              // 225536: 32 floats
#define LEN_OFF (BIAS_OFF + 128)             // 225664: 64 ints
#define BASE_OFF (LEN_OFF + 256)             // 225920: base_cnt[16] + base_done (u64)
#define SMEM_LOOP (BASE_OFF + 17 * 8)        // 226056

// precompute GEMM smem: 2 stages x (A 4x16KB + B 32KB)
#define PSTG_BYTES 98304
#define SMEM_PRE   (2 * PSTG_BYTES)

#define PX_ROWB 2112             // floats per (t,cta) px block: 64 rows x 33

// ---------------- device-global scratch (static; no cudaMalloc) ----------------
__device__ __align__(16) unsigned char g_zx[(size_t)TSTEPS*16*16384];  // x tiles [t*16+ch][hi8K|lo8K]
__device__ __align__(16) unsigned char g_zh[(size_t)2*16*16384];       // h tiles [buf*16+chl][hi8K|lo8K]
__device__ __align__(16) unsigned char g_Wxt[(size_t)32*16*32768];     // Wx tiles [ng*16+ch][hi16K|lo16K]
__device__ __align__(16) unsigned char g_Wht[(size_t)NCTA*NCHL*8192];  // Wh tiles [cta*16+ch][hi4K|lo4K]
__device__ float g_px[(size_t)TSTEPS*NCTA*PX_ROWB];                    // x-projection [t][cta][b*33+c]
__device__ unsigned long long g_bar;           // init grid-barrier ticket (monotonic)
__device__ unsigned long long g_cnt[NCHL];     // per-h-chunk producer arrivals (monotonic)
__device__ unsigned long long g_done;          // per-CTA step-staging-complete arrivals (monotonic)

// ---------------- helpers ----------------
__host__ __device__ __forceinline__ uint32_t swz128(uint32_t x) { return x ^ ((x >> 3) & 0x70); }

__device__ __forceinline__ uint32_t smem_u32(const void* p) {
    uint32_t a;
    asm("{ .reg .u64 t; cvta.to.shared.u64 t, %1; cvt.u32.u64 %0, t; }" : "=r"(a) : "l"(p));
    return a;
}
union U4 { unsigned short s[8]; uint4 v; };
__device__ __forceinline__ void bf16split(float v, unsigned short& hi, unsigned short& lo) {
    __nv_bfloat16 h = __float2bfloat16_rn(v);
    float r = v - __bfloat162float(h);
    __nv_bfloat16 l = __float2bfloat16_rn(r);
    hi = reinterpret_cast<unsigned short&>(h);
    lo = reinterpret_cast<unsigned short&>(l);
}
__device__ __forceinline__ unsigned short bf16hi(float v) {
    __nv_bfloat16 h = __float2bfloat16_rn(v);
    return reinterpret_cast<unsigned short&>(h);
}
__device__ __forceinline__ unsigned long long ld_acq_u64(const unsigned long long* p) {
    unsigned long long v;
    asm volatile("ld.global.acquire.gpu.u64 %0, [%1];" : "=l"(v) : "l"(p) : "memory");
    return v;
}
__device__ __forceinline__ void cp16(uint32_t saddr, const void* gaddr) {
    asm volatile("cp.async.cg.shared.global [%0], [%1], 16;" :: "r"(saddr), "l"(gaddr));
}
__device__ __forceinline__ void cp_commit() { asm volatile("cp.async.commit_group;"); }
template <int N> __device__ __forceinline__ void cp_wait() {
    asm volatile("cp.async.wait_group %0;" :: "n"(N));
}
__device__ __forceinline__ void ldsm4(uint32_t& r0, uint32_t& r1, uint32_t& r2, uint32_t& r3, uint32_t a) {
    asm volatile("ldmatrix.sync.aligned.m8n8.x4.shared.b16 {%0,%1,%2,%3}, [%4];"
                 : "=r"(r0), "=r"(r1), "=r"(r2), "=r"(r3) : "r"(a));
}
__device__ __forceinline__ void ldsm2(uint32_t& r0, uint32_t& r1, uint32_t a) {
    asm volatile("ldmatrix.sync.aligned.m8n8.x2.shared.b16 {%0,%1}, [%2];"
                 : "=r"(r0), "=r"(r1) : "r"(a));
}
__device__ __forceinline__ void mma16816(float* d, uint32_t a0, uint32_t a1, uint32_t a2, uint32_t a3,
                                         uint32_t b0, uint32_t b1) {
    asm volatile("mma.sync.aligned.m16n8k16.row.col.f32.bf16.bf16.f32 "
                 "{%0,%1,%2,%3}, {%4,%5,%6,%7}, {%8,%9}, {%0,%1,%2,%3};"
                 : "+f"(d[0]), "+f"(d[1]), "+f"(d[2]), "+f"(d[3])
                 : "r"(a0), "r"(a1), "r"(a2), "r"(a3), "r"(b0), "r"(b1));
}
__device__ __forceinline__ void grid_sync_full() {
    __syncthreads();
    if (threadIdx.x == 0) {
        __threadfence();
        unsigned long long t = atomicAdd(&g_bar, 1ULL);
        unsigned long long target = (t / NCTA + 1ULL) * NCTA;
        while (*(volatile unsigned long long*)&g_bar < target) __nanosleep(64);
        __threadfence();
    }
    __syncthreads();
}
__device__ __forceinline__ float sigmoidf_(float x) { return 1.0f / (1.0f + expf(-x)); }

// ============ init 1: x -> pre-swizzled bf16 hi/lo SW128 tiles ============
__global__ void cvt_x_kernel(const float* __restrict__ batch) {
    int bid = blockIdx.x;                 // t*16 + ch
    int tid = threadIdx.x;                // 128
    int b = tid >> 1, half = tid & 1;
    int t = bid >> 4, ch = bid & 15;
    const float* src = batch + ((size_t)t * BATCH + b) * DIN + ch * 64 + half * 32;
    unsigned char* dhi = g_zx + (size_t)bid * 16384;
    unsigned char* dlo = dhi + 8192;
    #pragma unroll
    for (int q = 0; q < 4; ++q) {
        float v[8];
        *(float4*)&v[0] = *(const float4*)(src + q * 8);
        *(float4*)&v[4] = *(const float4*)(src + q * 8 + 4);
        U4 hi, lo;
        #pragma unroll
        for (int j = 0; j < 8; ++j) bf16split(v[j], hi.s[j], lo.s[j]);
        uint32_t off = swz128((uint32_t)b * 128 + (uint32_t)(half * 4 + q) * 16);
        *(uint4*)(dhi + off) = hi.v;
        *(uint4*)(dlo + off) = lo.v;
    }
}

// ============ init 2: W_x -> 128-col-group pre-swizzled tiles ============
__global__ void cvt_wx_kernel(const float* __restrict__ Wi, const float* __restrict__ Wf,
                              const float* __restrict__ Wc, const float* __restrict__ Wo) {
    int bid = blockIdx.x;                 // ng*16 + ch
    int ng = bid >> 4, ch = bid & 15;
    int tid = threadIdx.x;                // 256
    int j = tid >> 1, khalf = tid & 1;
    int q = j >> 5, c = j & 31, gate = c >> 3;
    int wcol = (4 * ng + q) * 8 + (c & 7);
    const float* Wsrc[4] = {Wi, Wf, Wc, Wo};
    const float* src = Wsrc[gate] + (size_t)(ch * 64 + khalf * 32) * DHID + wcol;
    unsigned char* dst = g_Wxt + (size_t)bid * 32768;
    #pragma unroll
    for (int qq = 0; qq < 4; ++qq) {
        U4 hi, lo;
        #pragma unroll
        for (int kk = 0; kk < 8; ++kk)
            bf16split(src[(size_t)(qq * 8 + kk) * DHID], hi.s[kk], lo.s[kk]);
        uint32_t off = swz128((uint32_t)j * 128 + (uint32_t)(khalf * 4 + qq) * 16);
        *(uint4*)(dst + off) = hi.v;
        *(uint4*)(dst + 16384 + off) = lo.v;
    }
}

// ============ init 3: W_h (K rows 1024..2047) -> per-CTA tiles ============
__global__ void cvt_wh_kernel(const float* __restrict__ Wi, const float* __restrict__ Wf,
                              const float* __restrict__ Wc, const float* __restrict__ Wo) {
    __shared__ float sraw[4][64][8];
    int bid = blockIdx.x;                 // cta*16 + ch
    int cta = bid >> 4, ch = bid & 15;
    int tid = threadIdx.x;                // 256
    const float* Wsrc[4] = {Wi, Wf, Wc, Wo};
    {
        int g = tid >> 6, kk = tid & 63;
        const float* s = Wsrc[g] + (size_t)(1024 + ch * 64 + kk) * DHID + cta * 8;
        float4 a = *(const float4*)s, b = *(const float4*)(s + 4);
        sraw[g][kk][0] = a.x; sraw[g][kk][1] = a.y; sraw[g][kk][2] = a.z; sraw[g][kk][3] = a.w;
        sraw[g][kk][4] = b.x; sraw[g][kk][5] = b.y; sraw[g][kk][6] = b.z; sraw[g][kk][7] = b.w;
    }
    __syncthreads();
    int c = tid >> 3, kkb = tid & 7;
    int g = c >> 3, dd = c & 7;
    U4 hi, lo;
    #pragma unroll
    for (int j = 0; j < 8; ++j) bf16split(sraw[g][kkb * 8 + j][dd], hi.s[j], lo.s[j]);
    unsigned char* dst = g_Wht + (size_t)bid * 8192;
    uint32_t off = swz128((uint32_t)c * 128 + (uint32_t)kkb * 16);
    *(uint4*)(dst + off) = hi.v;
    *(uint4*)(dst + 4096 + off) = lo.v;
}

// ============ precompute GEMM: px[t][cta][b,32c] = x_t @ W_x (3-term split) ============
__global__ __launch_bounds__(256, 1)
void gemm_x_kernel() {
    extern __shared__ __align__(1024) unsigned char sm[];
    const uint32_t smem = smem_u32(sm);
    const int ng = blockIdx.x;
    const int tg = blockIdx.y;
    const int tid = threadIdx.x, wid = tid >> 5, lane = tid & 31;
    const int mt = wid & 3;
    const int nh = wid >> 2;
    const int lane16 = lane & 15;
    const int usel_a = lane >> 4;
    const int usel_b = (lane16 >> 3) & 1;

    int aoff[4][4];
    #pragma unroll
    for (int mi = 0; mi < 4; ++mi) {
        int arow = mi * 16 + lane16, arx = (arow & 7) << 4;
        #pragma unroll
        for (int ks = 0; ks < 4; ++ks)
            aoff[mi][ks] = arow * 128 + ((32 * ks + 16 * usel_a) ^ arx);
    }
    int boff[8][4];
    #pragma unroll
    for (int ni = 0; ni < 8; ++ni) {
        int brow = nh * 64 + ni * 8 + (lane16 & 7), brx = (brow & 7) << 4;
        #pragma unroll
        for (int ks = 0; ks < 4; ++ks)
            boff[ni][ks] = brow * 128 + ((32 * ks + 16 * usel_b) ^ brx);
    }

    float acc[4][8][4];
    #pragma unroll
    for (int mi = 0; mi < 4; ++mi)
        #pragma unroll
        for (int ni = 0; ni < 8; ++ni)
            #pragma unroll
            for (int q = 0; q < 4; ++q) acc[mi][ni][q] = 0.0f;

    auto issueP = [&](int ch) {
        uint32_t sb = smem + (uint32_t)(ch & 1) * PSTG_BYTES;
        #pragma unroll
        for (int i = 0; i < 16; ++i) {
            int j = tid + i * 256;
            int tt = j >> 10, off = j & 1023;
            cp16(sb + tt * 16384 + off * 16,
                 g_zx + ((size_t)(tg * 4 + tt) * 16 + ch) * 16384 + off * 16);
        }
        #pragma unroll
        for (int i = 0; i < 8; ++i) {
            int j = tid + i * 256;
            cp16(sb + 65536 + j * 16, g_Wxt + ((size_t)(ng * 16 + ch)) * 32768 + j * 16);
        }
        cp_commit();
    };

    issueP(0);
    for (int ch = 0; ch < 16; ++ch) {
        if (ch + 1 < 16) { issueP(ch + 1); cp_wait<1>(); }
        else             cp_wait<0>();
        __syncthreads();
        uint32_t sb  = smem + (uint32_t)(ch & 1) * PSTG_BYTES;
        uint32_t zhi = sb + mt * 16384, zlo = zhi + 8192;
        uint32_t bhi = sb + 65536, blo = bhi + 16384;
        #pragma unroll
        for (int ks = 0; ks < 4; ++ks) {
            uint32_t zh[4][4], zl[4][4], wf[8][2];
            #pragma unroll
            for (int mi = 0; mi < 4; ++mi) ldsm4(zh[mi][0], zh[mi][1], zh[mi][2], zh[mi][3], zhi + aoff[mi][ks]);
            #pragma unroll
            for (int ni = 0; ni < 8; ++ni) ldsm2(wf[ni][0], wf[ni][1], bhi + boff[ni][ks]);
            #pragma unroll
            for (int mi = 0; mi < 4; ++mi)
                #pragma unroll
                for (int ni = 0; ni < 8; ++ni)
                    mma16816(acc[mi][ni], zh[mi][0], zh[mi][1], zh[mi][2], zh[mi][3], wf[ni][0], wf[ni][1]);
            #pragma unroll
            for (int mi = 0; mi < 4; ++mi) ldsm4(zl[mi][0], zl[mi][1], zl[mi][2], zl[mi][3], zlo + aoff[mi][ks]);
            #pragma unroll
            for (int mi = 0; mi < 4; ++mi)
                #pragma unroll
                for (int ni = 0; ni < 8; ++ni)
                    mma16816(acc[mi][ni], zl[mi][0], zl[mi][1], zl[mi][2], zl[mi][3], wf[ni][0], wf[ni][1]);
            #pragma unroll
            for (int ni = 0; ni < 8; ++ni) ldsm2(wf[ni][0], wf[ni][1], blo + boff[ni][ks]);
            #pragma unroll
            for (int mi = 0; mi < 4; ++mi)
                #pragma unroll
                for (int ni = 0; ni < 8; ++ni)
                    mma16816(acc[mi][ni], zh[mi][0], zh[mi][1], zh[mi][2], zh[mi][3], wf[ni][0], wf[ni][1]);
        }
        __syncthreads();
    }

    const int t = tg * 4 + mt;
    #pragma unroll
    for (int mi = 0; mi < 4; ++mi) {
        int r0 = mi * 16 + (lane >> 2);
        #pragma unroll
        for (int ni = 0; ni < 8; ++ni) {
            int j = nh * 64 + ni * 8 + (lane & 3) * 2;
            int q = j >> 5, c = j & 31;
            float* base = g_px + ((size_t)t * NCTA + 4 * ng + q) * PX_ROWB;
            base[r0 * 33 + c]           = acc[mi][ni][0];
            base[r0 * 33 + c + 1]       = acc[mi][ni][1];
            base[(r0 + 8) * 33 + c]     = acc[mi][ni][2];
            base[(r0 + 8) * 33 + c + 1] = acc[mi][ni][3];
        }
    }
}

// ============ h tile writer (init only; epilogue writes per-thread) ============
__device__ __forceinline__ void store_h_tiles(int nbuf, int cta, int b, const float* h8) {
    int chl = cta >> 3, kkb = cta & 7;
    U4 hi, lo;
    #pragma unroll
    for (int j = 0; j < 8; ++j) bf16split(h8[j], hi.s[j], lo.s[j]);
    uint32_t off = swz128((uint32_t)b * 128 + (uint32_t)kkb * 16);
    unsigned char* base = g_zh + ((size_t)nbuf * 16 + chl) * 16384;
    *(uint4*)(base + off) = hi.v;
    *(uint4*)(base + 8192 + off) = lo.v;
}

// ============ persistent recurrent kernel: per-chunk dataflow sync ============
__global__ __launch_bounds__(NTHR, 1)
void lstm_mma_kernel(const int* __restrict__ lengths, const float* __restrict__ c0,
                     const float* __restrict__ bi, const float* __restrict__ bff,
                     const float* __restrict__ bc, const float* __restrict__ bo,
                     float* __restrict__ out) {
    extern __shared__ __align__(1024) unsigned char sm[];
    const uint32_t smem = smem_u32(sm);
    float* px_s   = (float*)(sm + PX_OFF);
    float* pp_s   = (float*)(sm + PP_OFF);     // [4][64*34]
    float* c_s    = (float*)(sm + C_OFF);      // [512]
    float* bias_s = (float*)(sm + BIAS_OFF);   // [32]
    int*   len_s  = (int*)(sm + LEN_OFF);      // [64]
    unsigned long long* base_s = (unsigned long long*)(sm + BASE_OFF);  // [16]=cnt, [16]=done

    const int tid = threadIdx.x, wid = tid >> 5, lane = tid & 31;
    const int cta = blockIdx.x;
    const int dbase = cta * 8;

    // --- baseline snapshot of monotonic counters (pre-barrier: stable at kernel entry) ---
    if (tid < NCHL) base_s[tid] = g_cnt[tid];
    if (tid == NCHL) base_s[NCHL] = g_done;

    // warp roles: mgroup (rows 32*mg..), kslice (k-residue within chunk)
    const int mg = wid & 1, kslice = wid >> 1;
    const int lane16 = lane & 15;
    const int usel_a = lane >> 4;
    const int usel_b = (lane16 >> 3) & 1;
    int aoff[2], boff[4];
    #pragma unroll
    for (int mi = 0; mi < 2; ++mi) {
        int arow = mg * 32 + mi * 16 + lane16, arx = (arow & 7) << 4;
        aoff[mi] = arow * 128 + ((32 * kslice + 16 * usel_a) ^ arx);
    }
    #pragma unroll
    for (int ni = 0; ni < 4; ++ni) {
        int brow = ni * 8 + (lane16 & 7), brx = (brow & 7) << 4;
        boff[ni] = brow * 128 + ((32 * kslice + 16 * usel_b) ^ brx);
    }

    // ---- init: W_h -> SMEM (resident) ----
    {
        const unsigned char* wsrc = g_Wht + (size_t)cta * (NCHL * 8192);
        for (int i = tid; i < 8192; i += NTHR) cp16(smem + WOFF + i * 16, wsrc + (size_t)i * 16);
        cp_commit(); cp_wait<0>();
    }
    for (int j = tid; j < 512; j += NTHR) c_s[j] = c0[dbase + (j & 7)];
    if (tid < 32) bias_s[tid] = ((tid >> 3) == 0 ? bi : (tid >> 3) == 1 ? bff :
                                 (tid >> 3) == 2 ? bc : bo)[dbase + (tid & 7)];
    if (tid < BATCH) {
        len_s[tid] = lengths[tid];
        float h0[8];
        #pragma unroll
        for (int dd = 0; dd < 8; ++dd) h0[dd] = tanhf(c0[dbase + dd]);
        store_h_tiles(0, cta, tid, h0);
    }
    grid_sync_full();   // h0 + baselines published before any arrivals

    const int chl = cta >> 3, kkb = cta & 7;   // epilogue h-tile coords

    // ---- recurrence (no full barrier; per-chunk producer counters) ----
    for (int t = 0; t < TSTEPS; ++t) {
        const int buf = t & 1;

        auto issue = [&](int ci) {
            // dataflow wait: 8 producer CTAs of h-chunk ci must have done step t-1 epilogue
            const unsigned long long need = base_s[ci] + (unsigned long long)(8 * t);
            while (ld_acq_u64(&g_cnt[ci]) < need) { }
            const unsigned char* srcz = g_zh + ((size_t)buf * 16 + ci) * 16384;
            uint32_t sb = smem + (uint32_t)(ci % NSTG) * ZSTG;
            #pragma unroll
            for (int i = 0; i < 4; ++i) {
                int j = tid + i * NTHR;
                cp16(sb + j * 16, srcz + (size_t)j * 16);
            }
            if (ci == 0) {
                const unsigned char* srcp =
                    (const unsigned char*)(g_px + ((size_t)t * NCTA + cta) * PX_ROWB);
                for (int i = tid; i < 528; i += NTHR) cp16(smem + PX_OFF + i * 16, srcp + (size_t)i * 16);
            }
            cp_commit();
        };

        float acc[2][4][4];
        #pragma unroll
        for (int mi = 0; mi < 2; ++mi)
            #pragma unroll
            for (int ni = 0; ni < 4; ++ni)
                #pragma unroll
                for (int q = 0; q < 4; ++q) acc[mi][ni][q] = 0.0f;

        issue(0); issue(1);
        for (int ch = 0; ch < NCHL; ++ch) {
            if (ch < NCHL - 1) cp_wait<1>();
            else               cp_wait<0>();
            __syncthreads();
            if (ch + 2 < NCHL) issue(ch + 2);   // post-sync: freed stage is safe to refill

            const uint32_t zb  = smem + (uint32_t)(ch % NSTG) * ZSTG;
            const uint32_t zhi = zb, zlo = zb + 8192;
            const uint32_t whi = smem + WOFF + (uint32_t)ch * 8192, wlo = whi + 4096;

            uint32_t ah[2][4], al[2][4], bh[4][2], bl[4][2];
            #pragma unroll
            for (int mi = 0; mi < 2; ++mi) {
                ldsm4(ah[mi][0], ah[mi][1], ah[mi][2], ah[mi][3], zhi + aoff[mi]);
                ldsm4(al[mi][0], al[mi][1], al[mi][2], al[mi][3], zlo + aoff[mi]);
            }
            #pragma unroll
            for (int ni = 0; ni < 4; ++ni) {
                ldsm2(bh[ni][0], bh[ni][1], whi + boff[ni]);
                ldsm2(bl[ni][0], bl[ni][1], wlo + boff[ni]);
            }
            #pragma unroll
            for (int mi = 0; mi < 2; ++mi)
                #pragma unroll
                for (int ni = 0; ni < 4; ++ni) {
                    mma16816(acc[mi][ni], ah[mi][0], ah[mi][1], ah[mi][2], ah[mi][3], bh[ni][0], bh[ni][1]);
                    mma16816(acc[mi][ni], ah[mi][0], ah[mi][1], ah[mi][2], ah[mi][3], bl[ni][0], bl[ni][1]);
                    mma16816(acc[mi][ni], al[mi][0], al[mi][1], al[mi][2], al[mi][3], bh[ni][0], bh[ni][1]);
                }
        }

        // ---- gather K-split partials (warp-private slices; stride 34 keeps float2 aligned) ----
        {
            float* pp = pp_s + kslice * PP_SLICE;
            #pragma unroll
            for (int mi = 0; mi < 2; ++mi) {
                int r0 = mg * 32 + mi * 16 + (lane >> 2);
                #pragma unroll
                for (int ni = 0; ni < 4; ++ni) {
                    int c = ni * 8 + (lane & 3) * 2;
                    *(float2*)&pp[r0 * PP_STRIDE + c]       = make_float2(acc[mi][ni][0], acc[mi][ni][1]);
                    *(float2*)&pp[(r0 + 8) * PP_STRIDE + c] = make_float2(acc[mi][ni][2], acc[mi][ni][3]);
                }
            }
        }
        __syncthreads();   // also: all threads past cp_wait<0> -> all h reads of step t complete

        // signal: this CTA finished reading step t's h tiles
        if (tid == 0) atomicAdd(&g_done, 1ULL);

        // ---- epilogue: all 256 threads, 2 cells each ----
        {
            // WAR guard: overwriting h written at step t-2, read during step t-1 by all CTAs
            if (t >= 1) {
                const unsigned long long needd = base_s[NCHL] + (unsigned long long)(NCTA * t);
                while (ld_acq_u64(&g_done) < needd) { }
            }
            const int b = tid >> 2, dd0 = (tid & 3) * 2;
            const int myl = len_s[b];
            const int bo34 = b * PP_STRIDE, bo33 = b * 33;
            unsigned short hhw[2], hlw[2];
            float h2[2];
            #pragma unroll
            for (int r = 0; r < 2; ++r) {
                const int dd = dd0 + r;
                float pre[4];
                #pragma unroll
                for (int g = 0; g < 4; ++g) {
                    const int c = g * 8 + dd;
                    pre[g] = px_s[bo33 + c] + bias_s[c]
                           + pp_s[bo34 + c] + pp_s[PP_SLICE + bo34 + c]
                           + pp_s[2 * PP_SLICE + bo34 + c] + pp_s[3 * PP_SLICE + bo34 + c];
                }
                float ig = sigmoidf_(pre[0]), fg = sigmoidf_(pre[1]);
                float gg = tanhf(pre[2]),     og = sigmoidf_(pre[3]);
                float cn = fg * c_s[b * 8 + dd] + ig * gg;
                float h  = og * tanhf(cn);
                if (t >= myl) h = 0.0f;
                c_s[b * 8 + dd] = cn;
                __nv_bfloat16 hb = __float2bfloat16_rn(h);
                hhw[r] = reinterpret_cast<unsigned short&>(hb);
                hlw[r] = bf16hi(h - __bfloat162float(hb));
                h2[r] = h;
            }
            // h pair -> global tiles (hi/lo) + out
            unsigned char* base = g_zh + ((size_t)(buf ^ 1) * 16 + chl) * 16384;
            uint32_t off = swz128((uint32_t)b * 128 + (uint32_t)kkb * 16) + (uint32_t)dd0 * 2;
            *(uint32_t*)(base + off)        = (uint32_t)hhw[0] | ((uint32_t)hhw[1] << 16);
            *(uint32_t*)(base + 8192 + off) = (uint32_t)hlw[0] | ((uint32_t)hlw[1] << 16);
            *(float2*)(out + ((size_t)t * BATCH + b) * DHID + dbase + dd0) = make_float2(h2[0], h2[1]);
        }
        __syncthreads();
        if (tid == 0) {        // producer arrive for our h chunk (post-sync fence covers all stores)
            __threadfence();
            atomicAdd(&g_cnt[chl], 1ULL);
        }
    }
}

extern "C" void kernel_launch(void* const* d_in, const int* in_sizes, int n_in,
                              void* d_out, int out_size) {
    const float* batch   = (const float*)d_in[0];
    const int*   lengths = (const int*)  d_in[1];
    const float* c0      = (const float*)d_in[2];
    const float* Wi = (const float*)d_in[3];
    const float* bi = (const float*)d_in[4];
    const float* Wf = (const float*)d_in[5];
    const float* bf = (const float*)d_in[6];
    const float* Wc = (const float*)d_in[7];
    const float* bc = (const float*)d_in[8];
    const float* Wo = (const float*)d_in[9];
    const float* bo = (const float*)d_in[10];
    float* out = (float*)d_out;

    cvt_x_kernel<<<TSTEPS * 16, 128>>>(batch);
    cvt_wx_kernel<<<32 * 16, 256>>>(Wi, Wf, Wc, Wo);
    cvt_wh_kernel<<<NCTA * NCHL, 256>>>(Wi, Wf, Wc, Wo);

    cudaFuncSetAttribute(gemm_x_kernel, cudaFuncAttributeMaxDynamicSharedMemorySize, SMEM_PRE);
    gemm_x_kernel<<<dim3(32, 128), 256, SMEM_PRE>>>();

    cudaFuncSetAttribute(lstm_mma_kernel, cudaFuncAttributeMaxDynamicSharedMemorySize, SMEM_LOOP);
    lstm_mma_kernel<<<NCTA, NTHR, SMEM_LOOP>>>(lengths, c0, bi, bf, bc, bo, out);
}

// round 10
// speedup vs baseline: 1.4537x; 1.4537x over previous
#include <cuda_runtime.h>
#include <cuda_bf16.h>
#include <cstdint>
#include <math.h>

// ---------------- problem constants ----------------
#define TSTEPS 512
#define BATCH  64
#define DIN    1024
#define DHID   1024

// ---------------- persistent-loop config ----------------
#define NCTA 128                 // persistent CTAs; CTA owns 8 hidden dims = 32 gemm cols
#define NTHR 256                 // 8 warps: mgroup = wid&1, kslice = wid>>1
#define NCHL 16                  // recurrent K chunks (1024/64)

// loop SMEM layout (bytes)
#define ZSTG    16384            // per stage: zhi 8K | zlo 8K
#define NSTG    3
#define WOFF    (NSTG * ZSTG)                // 49152 : W_h resident 128KB
#define PX_OFF  (WOFF + 131072)              // 180224: px 64x33 floats = 8448
#define PP_STRIDE 34
#define PP_SLICE  (BATCH * PP_STRIDE)        // 2176 floats per k-slice
#define PP_OFF  (PX_OFF + 8448)              // 188672: pre_part [4][2176] floats = 34816
#define C_OFF   (PP_OFF + 34816)             // 223488: c state 512 floats
#define BIAS_OFF (C_OFF + 2048)              // 225536: 32 floats
#define LEN_OFF (BIAS_OFF + 128)             // 225664: 64 ints
#define TGT_OFF (LEN_OFF + 256)              // 225920
#define SMEM_LOOP (TGT_OFF + 16)             // 225936

// precompute GEMM smem: 2 stages x (A 4x16KB + B 32KB)
#define PSTG_BYTES 98304
#define SMEM_PRE   (2 * PSTG_BYTES)

#define PX_ROWB 2112             // floats per (t,cta) px block: 64 rows x 33

// ---------------- device-global scratch (static; no cudaMalloc) ----------------
__device__ __align__(16) unsigned char g_zx[(size_t)TSTEPS*16*16384];  // x tiles [t*16+ch][hi8K|lo8K]
__device__ __align__(16) unsigned char g_zh[(size_t)2*16*16384];       // h tiles [buf*16+chl][hi8K|lo8K]
__device__ __align__(16) unsigned char g_Wxt[(size_t)32*16*32768];     // Wx tiles [ng*16+ch][hi16K|lo16K]
__device__ __align__(16) unsigned char g_Wht[(size_t)NCTA*NCHL*8192];  // Wh tiles [cta*16+ch][hi4K|lo4K]
__device__ float g_px[(size_t)TSTEPS*NCTA*PX_ROWB];                    // x-projection [t][cta][b*33+c]
__device__ unsigned long long g_bar;   // monotonic grid-barrier ticket

// ---------------- helpers ----------------
__host__ __device__ __forceinline__ uint32_t swz128(uint32_t x) { return x ^ ((x >> 3) & 0x70); }

__device__ __forceinline__ uint32_t smem_u32(const void* p) {
    uint32_t a;
    asm("{ .reg .u64 t; cvta.to.shared.u64 t, %1; cvt.u32.u64 %0, t; }" : "=r"(a) : "l"(p));
    return a;
}
union U4 { unsigned short s[8]; uint4 v; };
__device__ __forceinline__ void bf16split(float v, unsigned short& hi, unsigned short& lo) {
    __nv_bfloat16 h = __float2bfloat16_rn(v);
    float r = v - __bfloat162float(h);
    __nv_bfloat16 l = __float2bfloat16_rn(r);
    hi = reinterpret_cast<unsigned short&>(h);
    lo = reinterpret_cast<unsigned short&>(l);
}
__device__ __forceinline__ unsigned short bf16hi(float v) {
    __nv_bfloat16 h = __float2bfloat16_rn(v);
    return reinterpret_cast<unsigned short&>(h);
}
__device__ __forceinline__ void cp16(uint32_t saddr, const void* gaddr) {
    asm volatile("cp.async.cg.shared.global [%0], [%1], 16;" :: "r"(saddr), "l"(gaddr));
}
__device__ __forceinline__ void cp_commit() { asm volatile("cp.async.commit_group;"); }
template <int N> __device__ __forceinline__ void cp_wait() {
    asm volatile("cp.async.wait_group %0;" :: "n"(N));
}
__device__ __forceinline__ void ldsm4(uint32_t& r0, uint32_t& r1, uint32_t& r2, uint32_t& r3, uint32_t a) {
    asm volatile("ldmatrix.sync.aligned.m8n8.x4.shared.b16 {%0,%1,%2,%3}, [%4];"
                 : "=r"(r0), "=r"(r1), "=r"(r2), "=r"(r3) : "r"(a));
}
__device__ __forceinline__ void ldsm2(uint32_t& r0, uint32_t& r1, uint32_t a) {
    asm volatile("ldmatrix.sync.aligned.m8n8.x2.shared.b16 {%0,%1}, [%2];"
                 : "=r"(r0), "=r"(r1) : "r"(a));
}
__device__ __forceinline__ void mma16816(float* d, uint32_t a0, uint32_t a1, uint32_t a2, uint32_t a3,
                                         uint32_t b0, uint32_t b1) {
    asm volatile("mma.sync.aligned.m16n8k16.row.col.f32.bf16.bf16.f32 "
                 "{%0,%1,%2,%3}, {%4,%5,%6,%7}, {%8,%9}, {%0,%1,%2,%3};"
                 : "+f"(d[0]), "+f"(d[1]), "+f"(d[2]), "+f"(d[3])
                 : "r"(a0), "r"(a1), "r"(a2), "r"(a3), "r"(b0), "r"(b1));
}
__device__ __forceinline__ void grid_sync_full() {
    __syncthreads();
    if (threadIdx.x == 0) {
        __threadfence();
        unsigned long long t = atomicAdd(&g_bar, 1ULL);
        unsigned long long target = (t / NCTA + 1ULL) * NCTA;
        while (*(volatile unsigned long long*)&g_bar < target) __nanosleep(64);
        __threadfence();
    }
    __syncthreads();
}
__device__ __forceinline__ float sigmoidf_(float x) { return 1.0f / (1.0f + expf(-x)); }

// ============ init 1: x -> pre-swizzled bf16 hi/lo SW128 tiles ============
__global__ void cvt_x_kernel(const float* __restrict__ batch) {
    int bid = blockIdx.x;                 // t*16 + ch
    int tid = threadIdx.x;                // 128
    int b = tid >> 1, half = tid & 1;
    int t = bid >> 4, ch = bid & 15;
    const float* src = batch + ((size_t)t * BATCH + b) * DIN + ch * 64 + half * 32;
    unsigned char* dhi = g_zx + (size_t)bid * 16384;
    unsigned char* dlo = dhi + 8192;
    #pragma unroll
    for (int q = 0; q < 4; ++q) {
        float v[8];
        *(float4*)&v[0] = *(const float4*)(src + q * 8);
        *(float4*)&v[4] = *(const float4*)(src + q * 8 + 4);
        U4 hi, lo;
        #pragma unroll
        for (int j = 0; j < 8; ++j) bf16split(v[j], hi.s[j], lo.s[j]);
        uint32_t off = swz128((uint32_t)b * 128 + (uint32_t)(half * 4 + q) * 16);
        *(uint4*)(dhi + off) = hi.v;
        *(uint4*)(dlo + off) = lo.v;
    }
}

// ============ init 2 (FUSED): W_x tiles (bid<512) + W_h tiles (bid>=512) ============
__global__ void cvt_w_kernel(const float* __restrict__ Wi, const float* __restrict__ Wf,
                             const float* __restrict__ Wc, const float* __restrict__ Wo) {
    __shared__ float sraw[4][64][8];
    const float* Wsrc[4] = {Wi, Wf, Wc, Wo};
    int tid = threadIdx.x;                // 256
    if (blockIdx.x < 512) {
        // ---- W_x -> 128-col-group pre-swizzled tiles ----
        int bid = blockIdx.x;             // ng*16 + ch
        int ng = bid >> 4, ch = bid & 15;
        int j = tid >> 1, khalf = tid & 1;
        int q = j >> 5, c = j & 31, gate = c >> 3;
        int wcol = (4 * ng + q) * 8 + (c & 7);
        const float* src = Wsrc[gate] + (size_t)(ch * 64 + khalf * 32) * DHID + wcol;
        unsigned char* dst = g_Wxt + (size_t)bid * 32768;
        #pragma unroll
        for (int qq = 0; qq < 4; ++qq) {
            U4 hi, lo;
            #pragma unroll
            for (int kk = 0; kk < 8; ++kk)
                bf16split(src[(size_t)(qq * 8 + kk) * DHID], hi.s[kk], lo.s[kk]);
            uint32_t off = swz128((uint32_t)j * 128 + (uint32_t)(khalf * 4 + qq) * 16);
            *(uint4*)(dst + off) = hi.v;
            *(uint4*)(dst + 16384 + off) = lo.v;
        }
    } else {
        // ---- W_h (K rows 1024..2047) -> per-CTA tiles ----
        int bid = blockIdx.x - 512;       // cta*16 + ch
        int cta = bid >> 4, ch = bid & 15;
        {
            int g = tid >> 6, kk = tid & 63;
            const float* s = Wsrc[g] + (size_t)(1024 + ch * 64 + kk) * DHID + cta * 8;
            float4 a = *(const float4*)s, b = *(const float4*)(s + 4);
            sraw[g][kk][0] = a.x; sraw[g][kk][1] = a.y; sraw[g][kk][2] = a.z; sraw[g][kk][3] = a.w;
            sraw[g][kk][4] = b.x; sraw[g][kk][5] = b.y; sraw[g][kk][6] = b.z; sraw[g][kk][7] = b.w;
        }
        __syncthreads();
        int c = tid >> 3, kkb = tid & 7;
        int g = c >> 3, dd = c & 7;
        U4 hi, lo;
        #pragma unroll
        for (int j = 0; j < 8; ++j) bf16split(sraw[g][kkb * 8 + j][dd], hi.s[j], lo.s[j]);
        unsigned char* dst = g_Wht + (size_t)bid * 8192;
        uint32_t off = swz128((uint32_t)c * 128 + (uint32_t)kkb * 16);
        *(uint4*)(dst + off) = hi.v;
        *(uint4*)(dst + 4096 + off) = lo.v;
    }
}

// ============ precompute GEMM: px[t][cta][b,32c] = x_t @ W_x (3-term split) ============
__global__ __launch_bounds__(256, 1)
void gemm_x_kernel() {
    extern __shared__ __align__(1024) unsigned char sm[];
    const uint32_t smem = smem_u32(sm);
    const int ng = blockIdx.x;
    const int tg = blockIdx.y;
    const int tid = threadIdx.x, wid = tid >> 5, lane = tid & 31;
    const int mt = wid & 3;
    const int nh = wid >> 2;
    const int lane16 = lane & 15;
    const int usel_a = lane >> 4;
    const int usel_b = (lane16 >> 3) & 1;

    int aoff[4][4];
    #pragma unroll
    for (int mi = 0; mi < 4; ++mi) {
        int arow = mi * 16 + lane16, arx = (arow & 7) << 4;
        #pragma unroll
        for (int ks = 0; ks < 4; ++ks)
            aoff[mi][ks] = arow * 128 + ((32 * ks + 16 * usel_a) ^ arx);
    }
    int boff[8][4];
    #pragma unroll
    for (int ni = 0; ni < 8; ++ni) {
        int brow = nh * 64 + ni * 8 + (lane16 & 7), brx = (brow & 7) << 4;
        #pragma unroll
        for (int ks = 0; ks < 4; ++ks)
            boff[ni][ks] = brow * 128 + ((32 * ks + 16 * usel_b) ^ brx);
    }

    float acc[4][8][4];
    #pragma unroll
    for (int mi = 0; mi < 4; ++mi)
        #pragma unroll
        for (int ni = 0; ni < 8; ++ni)
            #pragma unroll
            for (int q = 0; q < 4; ++q) acc[mi][ni][q] = 0.0f;

    auto issueP = [&](int ch) {
        uint32_t sb = smem + (uint32_t)(ch & 1) * PSTG_BYTES;
        #pragma unroll
        for (int i = 0; i < 16; ++i) {
            int j = tid + i * 256;
            int tt = j >> 10, off = j & 1023;
            cp16(sb + tt * 16384 + off * 16,
                 g_zx + ((size_t)(tg * 4 + tt) * 16 + ch) * 16384 + off * 16);
        }
        #pragma unroll
        for (int i = 0; i < 8; ++i) {
            int j = tid + i * 256;
            cp16(sb + 65536 + j * 16, g_Wxt + ((size_t)(ng * 16 + ch)) * 32768 + j * 16);
        }
        cp_commit();
    };

    issueP(0);
    for (int ch = 0; ch < 16; ++ch) {
        if (ch + 1 < 16) { issueP(ch + 1); cp_wait<1>(); }
        else             cp_wait<0>();
        __syncthreads();
        uint32_t sb  = smem + (uint32_t)(ch & 1) * PSTG_BYTES;
        uint32_t zhi = sb + mt * 16384, zlo = zhi + 8192;
        uint32_t bhi = sb + 65536, blo = bhi + 16384;
        #pragma unroll
        for (int ks = 0; ks < 4; ++ks) {
            uint32_t zh[4][4], zl[4][4], wf[8][2];
            #pragma unroll
            for (int mi = 0; mi < 4; ++mi) ldsm4(zh[mi][0], zh[mi][1], zh[mi][2], zh[mi][3], zhi + aoff[mi][ks]);
            #pragma unroll
            for (int ni = 0; ni < 8; ++ni) ldsm2(wf[ni][0], wf[ni][1], bhi + boff[ni][ks]);
            #pragma unroll
            for (int mi = 0; mi < 4; ++mi)
                #pragma unroll
                for (int ni = 0; ni < 8; ++ni)
                    mma16816(acc[mi][ni], zh[mi][0], zh[mi][1], zh[mi][2], zh[mi][3], wf[ni][0], wf[ni][1]);
            #pragma unroll
            for (int mi = 0; mi < 4; ++mi) ldsm4(zl[mi][0], zl[mi][1], zl[mi][2], zl[mi][3], zlo + aoff[mi][ks]);
            #pragma unroll
            for (int mi = 0; mi < 4; ++mi)
                #pragma unroll
                for (int ni = 0; ni < 8; ++ni)
                    mma16816(acc[mi][ni], zl[mi][0], zl[mi][1], zl[mi][2], zl[mi][3], wf[ni][0], wf[ni][1]);
            #pragma unroll
            for (int ni = 0; ni < 8; ++ni) ldsm2(wf[ni][0], wf[ni][1], blo + boff[ni][ks]);
            #pragma unroll
            for (int mi = 0; mi < 4; ++mi)
                #pragma unroll
                for (int ni = 0; ni < 8; ++ni)
                    mma16816(acc[mi][ni], zh[mi][0], zh[mi][1], zh[mi][2], zh[mi][3], wf[ni][0], wf[ni][1]);
        }
        __syncthreads();
    }

    const int t = tg * 4 + mt;
    #pragma unroll
    for (int mi = 0; mi < 4; ++mi) {
        int r0 = mi * 16 + (lane >> 2);
        #pragma unroll
        for (int ni = 0; ni < 8; ++ni) {
            int j = nh * 64 + ni * 8 + (lane & 3) * 2;
            int q = j >> 5, c = j & 31;
            float* base = g_px + ((size_t)t * NCTA + 4 * ng + q) * PX_ROWB;
            base[r0 * 33 + c]           = acc[mi][ni][0];
            base[r0 * 33 + c + 1]       = acc[mi][ni][1];
            base[(r0 + 8) * 33 + c]     = acc[mi][ni][2];
            base[(r0 + 8) * 33 + c + 1] = acc[mi][ni][3];
        }
    }
}

// ============ h tile writer (init only; epilogue writes per-thread) ============
__device__ __forceinline__ void store_h_tiles(int nbuf, int cta, int b, const float* h8) {
    int chl = cta >> 3, kkb = cta & 7;
    U4 hi, lo;
    #pragma unroll
    for (int j = 0; j < 8; ++j) bf16split(h8[j], hi.s[j], lo.s[j]);
    uint32_t off = swz128((uint32_t)b * 128 + (uint32_t)kkb * 16);
    unsigned char* base = g_zh + ((size_t)nbuf * 16 + chl) * 16384;
    *(uint4*)(base + off) = hi.v;
    *(uint4*)(base + 8192 + off) = lo.v;
}

// ============ persistent recurrent kernel (K=1024, W_h in SMEM, K-split 4) ============
__global__ __launch_bounds__(NTHR, 1)
void lstm_mma_kernel(const int* __restrict__ lengths, const float* __restrict__ c0,
                     const float* __restrict__ bi, const float* __restrict__ bff,
                     const float* __restrict__ bc, const float* __restrict__ bo,
                     float* __restrict__ out) {
    extern __shared__ __align__(1024) unsigned char sm[];
    const uint32_t smem = smem_u32(sm);
    float* px_s   = (float*)(sm + PX_OFF);
    float* pp_s   = (float*)(sm + PP_OFF);     // [4][64*34]
    float* c_s    = (float*)(sm + C_OFF);      // [512]
    float* bias_s = (float*)(sm + BIAS_OFF);   // [32]
    int*   len_s  = (int*)(sm + LEN_OFF);      // [64]
    volatile unsigned long long* tgt_s = (volatile unsigned long long*)(sm + TGT_OFF);

    const int tid = threadIdx.x, wid = tid >> 5, lane = tid & 31;
    const int cta = blockIdx.x;
    const int dbase = cta * 8;

    // warp roles: mgroup (rows 32*mg..), kslice (k-residue within chunk)
    const int mg = wid & 1, kslice = wid >> 1;
    const int lane16 = lane & 15;
    const int usel_a = lane >> 4;
    const int usel_b = (lane16 >> 3) & 1;
    int aoff[2], boff[4];
    #pragma unroll
    for (int mi = 0; mi < 2; ++mi) {
        int arow = mg * 32 + mi * 16 + lane16, arx = (arow & 7) << 4;
        aoff[mi] = arow * 128 + ((32 * kslice + 16 * usel_a) ^ arx);
    }
    #pragma unroll
    for (int ni = 0; ni < 4; ++ni) {
        int brow = ni * 8 + (lane16 & 7), brx = (brow & 7) << 4;
        boff[ni] = brow * 128 + ((32 * kslice + 16 * usel_b) ^ brx);
    }

    // ---- init: W_h -> SMEM (resident) ----
    {
        const unsigned char* wsrc = g_Wht + (size_t)cta * (NCHL * 8192);
        for (int i = tid; i < 8192; i += NTHR) cp16(smem + WOFF + i * 16, wsrc + (size_t)i * 16);
        cp_commit(); cp_wait<0>();
    }
    for (int j = tid; j < 512; j += NTHR) c_s[j] = c0[dbase + (j & 7)];
    if (tid < 32) bias_s[tid] = ((tid >> 3) == 0 ? bi : (tid >> 3) == 1 ? bff :
                                 (tid >> 3) == 2 ? bc : bo)[dbase + (tid & 7)];
    if (tid < BATCH) {
        len_s[tid] = lengths[tid];
        float h0[8];
        #pragma unroll
        for (int dd = 0; dd < 8; ++dd) h0[dd] = tanhf(c0[dbase + dd]);
        store_h_tiles(0, cta, tid, h0);
    }
    if (tid == 0) *tgt_s = 0ULL;   // step-0 wait passes immediately
    grid_sync_full();

    const int chl = cta >> 3, kkb = cta & 7;   // epilogue h-tile coords

    // ---- recurrence ----
    for (int t = 0; t < TSTEPS; ++t) {
        const int buf = t & 1;

        // px prefetch (no h dependency) — overlaps the barrier wait below
        {
            const unsigned char* srcp =
                (const unsigned char*)(g_px + ((size_t)t * NCTA + cta) * PX_ROWB);
            for (int i = tid; i < 528; i += NTHR) cp16(smem + PX_OFF + i * 16, srcp + (size_t)i * 16);
            cp_commit();
        }

        // wait for all CTAs' step t-1 h (tid0 poll + fence, block consumer pattern)
        if (tid == 0) {
            unsigned long long tgt = *tgt_s;
            while (*(volatile unsigned long long*)&g_bar < tgt) __nanosleep(32);
            __threadfence();
        }
        __syncthreads();

        auto issue = [&](int ci) {
            const unsigned char* srcz = g_zh + ((size_t)buf * 16 + ci) * 16384;
            uint32_t sb = smem + (uint32_t)(ci % NSTG) * ZSTG;
            #pragma unroll
            for (int i = 0; i < 4; ++i) {
                int j = tid + i * NTHR;
                cp16(sb + j * 16, srcz + (size_t)j * 16);
            }
            cp_commit();
        };

        float acc[2][4][4];
        #pragma unroll
        for (int mi = 0; mi < 2; ++mi)
            #pragma unroll
            for (int ni = 0; ni < 4; ++ni)
                #pragma unroll
                for (int q = 0; q < 4; ++q) acc[mi][ni][q] = 0.0f;

        issue(0); issue(1);
        for (int ch = 0; ch < NCHL; ++ch) {
            if (ch < NCHL - 1) cp_wait<1>();   // also drains the px group early on
            else               cp_wait<0>();
            __syncthreads();
            if (ch + 2 < NCHL) issue(ch + 2);   // post-sync: freed stage is safe to refill

            const uint32_t zb  = smem + (uint32_t)(ch % NSTG) * ZSTG;
            const uint32_t zhi = zb, zlo = zb + 8192;
            const uint32_t whi = smem + WOFF + (uint32_t)ch * 8192, wlo = whi + 4096;

            uint32_t ah[2][4], al[2][4], bh[4][2], bl[4][2];
            #pragma unroll
            for (int mi = 0; mi < 2; ++mi) {
                ldsm4(ah[mi][0], ah[mi][1], ah[mi][2], ah[mi][3], zhi + aoff[mi]);
                ldsm4(al[mi][0], al[mi][1], al[mi][2], al[mi][3], zlo + aoff[mi]);
            }
            #pragma unroll
            for (int ni = 0; ni < 4; ++ni) {
                ldsm2(bh[ni][0], bh[ni][1], whi + boff[ni]);
                ldsm2(bl[ni][0], bl[ni][1], wlo + boff[ni]);
            }
            #pragma unroll
            for (int mi = 0; mi < 2; ++mi)
                #pragma unroll
                for (int ni = 0; ni < 4; ++ni) {
                    mma16816(acc[mi][ni], ah[mi][0], ah[mi][1], ah[mi][2], ah[mi][3], bh[ni][0], bh[ni][1]);
                    mma16816(acc[mi][ni], ah[mi][0], ah[mi][1], ah[mi][2], ah[mi][3], bl[ni][0], bl[ni][1]);
                    mma16816(acc[mi][ni], al[mi][0], al[mi][1], al[mi][2], al[mi][3], bh[ni][0], bh[ni][1]);
                }
        }

        // ---- gather K-split partials (warp-private slices; stride 34 keeps float2 aligned) ----
        {
            float* pp = pp_s + kslice * PP_SLICE;
            #pragma unroll
            for (int mi = 0; mi < 2; ++mi) {
                int r0 = mg * 32 + mi * 16 + (lane >> 2);
                #pragma unroll
                for (int ni = 0; ni < 4; ++ni) {
                    int c = ni * 8 + (lane & 3) * 2;
                    *(float2*)&pp[r0 * PP_STRIDE + c]       = make_float2(acc[mi][ni][0], acc[mi][ni][1]);
                    *(float2*)&pp[(r0 + 8) * PP_STRIDE + c] = make_float2(acc[mi][ni][2], acc[mi][ni][3]);
                }
            }
        }
        __syncthreads();

        // ---- epilogue: all 256 threads, 2 cells each; out-store deferred past the arrive ----
        const int b = tid >> 2, dd0 = (tid & 3) * 2;
        float h2[2];
        {
            const int myl = len_s[b];
            const int bo34 = b * PP_STRIDE, bo33 = b * 33;
            unsigned short hhw[2], hlw[2];
            #pragma unroll
            for (int r = 0; r < 2; ++r) {
                const int dd = dd0 + r;
                float pre[4];
                #pragma unroll
                for (int g = 0; g < 4; ++g) {
                    const int c = g * 8 + dd;
                    pre[g] = px_s[bo33 + c] + bias_s[c]
                           + pp_s[bo34 + c] + pp_s[PP_SLICE + bo34 + c]
                           + pp_s[2 * PP_SLICE + bo34 + c] + pp_s[3 * PP_SLICE + bo34 + c];
                }
                float ig = sigmoidf_(pre[0]), fg = sigmoidf_(pre[1]);
                float gg = tanhf(pre[2]),     og = sigmoidf_(pre[3]);
                float cn = fg * c_s[b * 8 + dd] + ig * gg;
                float h  = og * tanhf(cn);
                if (t >= myl) h = 0.0f;
                c_s[b * 8 + dd] = cn;
                __nv_bfloat16 hb = __float2bfloat16_rn(h);
                hhw[r] = reinterpret_cast<unsigned short&>(hb);
                hlw[r] = bf16hi(h - __bfloat162float(hb));
                h2[r] = h;
            }
            // h pair -> global tiles (hi/lo) — these are what other CTAs wait on
            unsigned char* base = g_zh + ((size_t)(buf ^ 1) * 16 + chl) * 16384;
            uint32_t off = swz128((uint32_t)b * 128 + (uint32_t)kkb * 16) + (uint32_t)dd0 * 2;
            *(uint32_t*)(base + off)        = (uint32_t)hhw[0] | ((uint32_t)hhw[1] << 16);
            *(uint32_t*)(base + 8192 + off) = (uint32_t)hlw[0] | ((uint32_t)hlw[1] << 16);
        }
        __syncthreads();
        if (tid == 0) {        // producer arrive (post-sync tid0 fence covers all threads' h stores)
            __threadfence();
            unsigned long long my = atomicAdd(&g_bar, 1ULL);
            *tgt_s = (my / NCTA + 1ULL) * NCTA;
        }
        // output store: off the inter-CTA critical path
        *(float2*)(out + ((size_t)t * BATCH + b) * DHID + dbase + dd0) = make_float2(h2[0], h2[1]);
    }
}

extern "C" void kernel_launch(void* const* d_in, const int* in_sizes, int n_in,
                              void* d_out, int out_size) {
    const float* batch   = (const float*)d_in[0];
    const int*   lengths = (const int*)  d_in[1];
    const float* c0      = (const float*)d_in[2];
    const float* Wi = (const float*)d_in[3];
    const float* bi = (const float*)d_in[4];
    const float* Wf = (const float*)d_in[5];
    const float* bf = (const float*)d_in[6];
    const float* Wc = (const float*)d_in[7];
    const float* bc = (const float*)d_in[8];
    const float* Wo = (const float*)d_in[9];
    const float* bo = (const float*)d_in[10];
    float* out = (float*)d_out;

    cvt_x_kernel<<<TSTEPS * 16, 128>>>(batch);
    cvt_w_kernel<<<512 + NCTA * NCHL, 256>>>(Wi, Wf, Wc, Wo);

    cudaFuncSetAttribute(gemm_x_kernel, cudaFuncAttributeMaxDynamicSharedMemorySize, SMEM_PRE);
    gemm_x_kernel<<<dim3(32, 128), 256, SMEM_PRE>>>();

    cudaFuncSetAttribute(lstm_mma_kernel, cudaFuncAttributeMaxDynamicSharedMemorySize, SMEM_LOOP);
    lstm_mma_kernel<<<NCTA, NTHR, SMEM_LOOP>>>(lengths, c0, bi, bf, bc, bo, out);
}